// round 11
// baseline (speedup 1.0000x reference)
#include <cuda_runtime.h>
#include <cuda_pipeline.h>
#include <math.h>
#include <stdint.h>

#define NTOK 16384
#define DDIM 2048
#define NEXP 64
#define TM   128
#define NBLK (NTOK / TM)      // 128 blocks
#define NTHR 512              // 16 warps
#define KC   64
#define NCHUNK (DDIM / KC)    // 32 chunks
#define APITCH 68             // A smem pitch (floats): conflict-free frag LDS
#define ASZ (TM * APITCH)     // 8704 f per buffer
#define BROW 264              // packed-B row stride (floats): 1056B ≡ 32 mod 128 -> conflict-free LDS.128
#define WBSZ (32 * BROW)      // 8448 f per buffer (32 (ks,l4) rows per chunk)
#define NOISE_STD (1.0f / 64.0f)
#define TF32_MASK 0xFFFFE000u

// smem float offsets (double-buffered, depth 2)
#define OFF_ARAW 0                       // 2 x 8704 = 17408
#define OFF_WB   (2 * ASZ)               // 2 x 8448 = 16896
#define SMEM_F   (OFF_WB + 2 * WBSZ)     // 34304 floats
#define SMEM_BYTES (SMEM_F * 4)          // 137216 B -> 1 CTA/SM

// device scratch (no cudaMalloc allowed)
__device__ float g_part_imp[NBLK][NEXP];
__device__ float g_part_p[NBLK][NEXP];
// packed W: [ks_g*4+l4][n][4] = {wh(k), wh(k+4), wl(k), wl(k+4)}, k = ks_g*8+l4
__device__ float g_wb[DDIM * NEXP * 2];
__device__ int   g_ctr;

__device__ __forceinline__ uint32_t tf32_of(float f) {
    uint32_t u;
    asm("cvt.rna.tf32.f32 %0, %1;" : "=r"(u) : "f"(f));
    return u;
}
__device__ __forceinline__ void mma_tf32(float* c, const uint32_t* a,
                                         uint32_t b0, uint32_t b1) {
    asm volatile(
        "mma.sync.aligned.m16n8k8.row.col.f32.tf32.tf32.f32 "
        "{%0,%1,%2,%3}, {%4,%5,%6,%7}, {%8,%9}, {%0,%1,%2,%3};"
        : "+f"(c[0]), "+f"(c[1]), "+f"(c[2]), "+f"(c[3])
        : "r"(a[0]), "r"(a[1]), "r"(a[2]), "r"(a[3]), "r"(b0), "r"(b1));
}
__device__ __forceinline__ bool gtv(float a, int ia, float b, int ib) {
    return (a > b) || (a == b && ia < ib);
}

// ---- prologue: split W once into packed tf32 hi/lo quads
__global__ void __launch_bounds__(256) wconv(const float* __restrict__ W) {
    const int idx = blockIdx.x * 256 + threadIdx.x;   // 512 blocks -> 131072 elems
    const int k = idx >> 6, n = idx & 63;
    const float w = W[idx];
    const float hf = __uint_as_float(tf32_of(w));
    const float lf = __uint_as_float(tf32_of(w - hf));
    const int ks = k >> 3, l4 = k & 3, half = (k >> 2) & 1;
    const int base = ((ks * 4 + l4) * 64 + n) * 4;
    g_wb[base + half]     = hf;
    g_wb[base + 2 + half] = lf;
}

__global__ void __launch_bounds__(NTHR)
router_main(const float* __restrict__ x, const float* __restrict__ bias_g,
            const float* __restrict__ noise, float* __restrict__ out) {
    extern __shared__ __align__(16) float sm[];

    const int tid  = threadIdx.x;
    const int lane = tid & 31;
    const int w    = tid >> 5;    // warp 0..15
    const int mg   = w & 7;       // m-tile: rows [mg*16, mg*16+16)
    const int ng   = w >> 3;      // n-group: cols [ng*32, ng*32+32)
    const int g    = lane >> 2;   // 0..7
    const int l4   = lane & 3;    // 0..3
    const int bm   = blockIdx.x * TM;

    // staging A: 4 threads per token row, 16 consecutive floats each
    const int tokS = tid >> 2;
    const int qS   = (tid & 3) * 16;
    const float* xsrc = x + (size_t)(bm + tokS) * DDIM + qS;
    // staging B: thread t copies 16 floats of packed row rB at offset oB
    const int rB = tid >> 4;        // 0..31
    const int oB = (tid & 15) * 16; // 0..240

    auto stage = [&](int c) {
        if (c < NCHUNK) {
            float* ad = sm + OFF_ARAW + (c & 1) * ASZ + tokS * APITCH + qS;
            const float* as = xsrc + c * KC;
#pragma unroll
            for (int i = 0; i < 4; i++)
                __pipeline_memcpy_async(ad + 4 * i, as + 4 * i, 16);
            float* bd = sm + OFF_WB + (c & 1) * WBSZ + rB * BROW + oB;
            const float* bs = g_wb + c * 8192 + rB * 256 + oB;
#pragma unroll
            for (int i = 0; i < 4; i++)
                __pipeline_memcpy_async(bd + 4 * i, bs + 4 * i, 16);
        }
        __pipeline_commit();
    };

    float acc[4][4];
#pragma unroll
    for (int ni = 0; ni < 4; ni++)
#pragma unroll
        for (int r = 0; r < 4; r++) acc[ni][r] = 0.f;

    stage(0); stage(1);
    __pipeline_wait_prior(1);   // chunk 0 landed (thread-local)
    __syncthreads();            // chunk 0 visible block-wide

    const int r0 = mg * 16 + g;
    const int boq = (ng * 32 + g) * 4;   // float offset of this lane's B quad base

    for (int c = 0; c < NCHUNK; ++c) {
        // invariant: chunk c visible block-wide; chunk c+1 in flight
        const float* Ar = sm + OFF_ARAW + (c & 1) * ASZ;
        const float* Bs = sm + OFF_WB + (c & 1) * WBSZ + l4 * BROW;

        // fragment register double-buffer
        float  fA[2][4];
        float4 fB[2][4];
        {
            const int kk = l4;
            fA[0][0] = Ar[r0 * APITCH + kk];
            fA[0][1] = Ar[(r0 + 8) * APITCH + kk];
            fA[0][2] = Ar[r0 * APITCH + kk + 4];
            fA[0][3] = Ar[(r0 + 8) * APITCH + kk + 4];
#pragma unroll
            for (int ni = 0; ni < 4; ni++)
                fB[0][ni] = *(const float4*)(Bs + boq + ni * 32);
        }

#pragma unroll
        for (int ks = 0; ks < KC / 8; ks++) {
            const int cur = ks & 1, nxt = cur ^ 1;
            if (ks < KC / 8 - 1) {   // prefetch next ks fragments
                const int kk = (ks + 1) * 8 + l4;
                fA[nxt][0] = Ar[r0 * APITCH + kk];
                fA[nxt][1] = Ar[(r0 + 8) * APITCH + kk];
                fA[nxt][2] = Ar[r0 * APITCH + kk + 4];
                fA[nxt][3] = Ar[(r0 + 8) * APITCH + kk + 4];
                const float* Bp = Bs + (ks + 1) * 4 * BROW + boq;
#pragma unroll
                for (int ni = 0; ni < 4; ni++)
                    fB[nxt][ni] = *(const float4*)(Bp + ni * 32);
            }
            // exact mask split of A (ah, al both valid tf32 patterns)
            uint32_t ah[4], al[4];
#pragma unroll
            for (int r = 0; r < 4; r++) {
                ah[r] = __float_as_uint(fA[cur][r]) & TF32_MASK;
                al[r] = __float_as_uint(fA[cur][r] - __uint_as_float(ah[r])) & TF32_MASK;
            }
            // term-major: same-acc RAW distance 4
#pragma unroll
            for (int ni = 0; ni < 4; ni++)
                mma_tf32(acc[ni], ah, __float_as_uint(fB[cur][ni].x),
                         __float_as_uint(fB[cur][ni].y));           // hh
#pragma unroll
            for (int ni = 0; ni < 4; ni++)
                mma_tf32(acc[ni], ah, __float_as_uint(fB[cur][ni].z),
                         __float_as_uint(fB[cur][ni].w));           // hl
#pragma unroll
            for (int ni = 0; ni < 4; ni++)
                mma_tf32(acc[ni], al, __float_as_uint(fB[cur][ni].x),
                         __float_as_uint(fB[cur][ni].y));           // lh
        }

        __syncthreads();           // all reads of buf (c&1) complete block-wide
        stage(c + 2);              // overwrite buf (c&1) (async)
        __pipeline_wait_prior(1);  // thread-local: chunk c+1 landed
        __syncthreads();           // cross-thread: chunk c+1 visible
    }

    // ---- store C into Ls[128][66] (reuses ARAW region; loop ended with sync)
    float* Ls = sm;
#pragma unroll
    for (int ni = 0; ni < 4; ni++) {
        const int row = mg * 16 + g;
        const int col = ng * 32 + ni * 8 + l4 * 2;
        *(float2*)(Ls + row * 66 + col) = make_float2(acc[ni][0], acc[ni][1]);
        *(float2*)(Ls + (row + 8) * 66 + col) = make_float2(acc[ni][2], acc[ni][3]);
    }
    __syncthreads();

    // ---- per-token epilogue: warp w handles tokens [w*8, w*8+8)
    const int e0 = 2 * lane;
    const int e1 = 2 * lane + 1;
    const float bb0 = __ldg(bias_g + e0);
    const float bb1 = __ldg(bias_g + e1);

    float imp0 = 0.f, imp1 = 0.f, pa0 = 0.f, pa1 = 0.f;

    for (int tt = 0; tt < 8; ++tt) {
        const int tl = w * 8 + tt;
        const int t  = bm + tl;
        const float2 L2 = *(const float2*)(Ls + tl * 66 + e0);
        const float l0 = L2.x + bb0, l1 = L2.y + bb1;

        float mx = fmaxf(l0, l1);
#pragma unroll
        for (int off = 16; off; off >>= 1)
            mx = fmaxf(mx, __shfl_xor_sync(0xffffffffu, mx, off));
        const float s0 = __expf(l0 - mx);
        const float s1 = __expf(l1 - mx);
        float ss = s0 + s1;
#pragma unroll
        for (int off = 16; off; off >>= 1)
            ss += __shfl_xor_sync(0xffffffffu, ss, off);
        const float rs = 1.0f / ss;
        imp0 += s0 * rs;
        imp1 += s1 * rs;

        const float2 nz = *(const float2*)(noise + (size_t)t * NEXP + e0);
        const float n0 = fmaf(NOISE_STD, nz.x, l0);
        const float n1 = fmaf(NOISE_STD, nz.y, l1);
        float v1, v2;
        int i1, i2;
        if (n0 >= n1) { v1 = n0; i1 = e0; v2 = n1; i2 = e1; }
        else          { v1 = n1; i1 = e1; v2 = n0; i2 = e0; }
#pragma unroll
        for (int off = 16; off; off >>= 1) {
            const float ov1 = __shfl_xor_sync(0xffffffffu, v1, off);
            const int   oi1 = __shfl_xor_sync(0xffffffffu, i1, off);
            const float ov2 = __shfl_xor_sync(0xffffffffu, v2, off);
            const int   oi2 = __shfl_xor_sync(0xffffffffu, i2, off);
            if (gtv(ov1, oi1, v1, i1)) {
                if (gtv(v1, i1, ov2, oi2)) { v2 = v1; i2 = i1; }
                else                       { v2 = ov2; i2 = oi2; }
                v1 = ov1; i1 = oi1;
            } else if (gtv(ov1, oi1, v2, i2)) {
                v2 = ov1; i2 = oi1;
            }
        }

        const float ee = __expf(v2 - v1);
        const float g1 = 1.0f / (1.0f + ee);
        const float g2 = ee * g1;

        const float z0 = (v2 - l0) * 64.0f;
        const float z1 = (v2 - l1) * 64.0f;
        pa0 += normcdff(-z0);
        pa1 += normcdff(-z1);

        if (lane == 0) {
            out[2 * t + 0] = g1;
            out[2 * t + 1] = g2;
            out[2 * NTOK + 2 * t + 0] = (float)i1;
            out[2 * NTOK + 2 * t + 1] = (float)i2;
        }
    }

    // ---- block partials (deterministic layout; 16 warps)
    float* redI = sm + 8448;          // [16][64]
    float* redP = sm + 8448 + 1024;   // [16][64]
    redI[w * 64 + e0] = imp0;
    redI[w * 64 + e1] = imp1;
    redP[w * 64 + e0] = pa0;
    redP[w * 64 + e1] = pa1;
    __syncthreads();
    if (tid < NEXP) {
        float si = 0.f, sp = 0.f;
#pragma unroll
        for (int r = 0; r < 16; r++) {
            si += redI[r * 64 + tid];
            sp += redP[r * 64 + tid];
        }
        g_part_imp[blockIdx.x][tid] = si;
        g_part_p[blockIdx.x][tid]   = sp;
    }

    // ---- last CTA computes aux loss (fixed-order sums -> deterministic)
    __threadfence();
    __shared__ int s_ticket;
    if (tid == 0) s_ticket = atomicAdd(&g_ctr, 1);
    __syncthreads();
    if (s_ticket == NBLK - 1) {
        const int e = tid & 63;
        const int h = tid >> 6;  // 0..7
        float si = 0.f, sp = 0.f;
        for (int b = h * (NBLK / 8); b < (h + 1) * (NBLK / 8); ++b) {
            si += g_part_imp[b][e];
            sp += g_part_p[b][e];
        }
        float* sa = sm;          // reuse smem (post-sync); [8][64]
        float* sb = sm + 512;
        __syncthreads();
        sa[h * 64 + e] = si;
        sb[h * 64 + e] = sp;
        __syncthreads();
        if (tid == 0) {
            float ma = 0.f, mp = 0.f;
            float va = 0.f, vp = 0.f;
            float ia[NEXP], pa[NEXP];
            for (int i = 0; i < NEXP; i++) {
                float s1 = 0.f, s2 = 0.f;
                for (int hh = 0; hh < 8; hh++) {
                    s1 += sa[hh * 64 + i];
                    s2 += sb[hh * 64 + i];
                }
                ia[i] = s1;
                pa[i] = s2 * (1.0f / NTOK);
                ma += ia[i];
                mp += pa[i];
            }
            ma *= (1.0f / NEXP);
            mp *= (1.0f / NEXP);
            for (int i = 0; i < NEXP; i++) {
                const float da = ia[i] - ma;
                const float dp = pa[i] - mp;
                va += da * da;
                vp += dp * dp;
            }
            va *= (1.0f / (NEXP - 1));  // ddof=1
            vp *= (1.0f / (NEXP - 1));
            const float il = va / ((ma + 1e-8f) * (ma + 1e-8f));
            const float ll = vp / ((mp + 1e-8f) * (mp + 1e-8f));
            g_ctr = 0;  // reset for next graph replay
            out[4 * NTOK] = 0.5f * (il + ll);
        }
    }
}

extern "C" void kernel_launch(void* const* d_in, const int* in_sizes, int n_in,
                              void* d_out, int out_size) {
    const float* x     = (const float*)d_in[0];
    const float* W     = (const float*)d_in[1];
    const float* b     = (const float*)d_in[2];
    const float* noise = (const float*)d_in[3];
    float* out = (float*)d_out;

    cudaFuncSetAttribute(router_main, cudaFuncAttributeMaxDynamicSharedMemorySize, SMEM_BYTES);
    wconv<<<512, 256>>>(W);
    router_main<<<NBLK, NTHR, SMEM_BYTES>>>(x, b, noise, out);
}

// round 12
// speedup vs baseline: 1.1097x; 1.1097x over previous
#include <cuda_runtime.h>
#include <cuda_pipeline.h>
#include <math.h>
#include <stdint.h>

#define NTOK 16384
#define DDIM 2048
#define NEXP 64
#define TM   128
#define NBLK (NTOK / TM)      // 128 blocks
#define NTHR 1024             // 32 warps, 8 per SMSP
#define KC   64
#define NCHUNK (DDIM / KC)    // 32 chunks
#define APITCH 68             // A smem pitch (floats): conflict-free frag LDS
#define BPITCH 72             // B smem pitch (floats): conflict-free frag LDS
#define ASZ (TM * APITCH)     // 8704 f per buffer
#define BSZ (KC * BPITCH)     // 4608 f per buffer
#define NOISE_STD (1.0f / 64.0f)
#define TF32_MASK 0xFFFFE000u

// smem float offsets (double-buffered, depth 2) — identical to R10 best
#define OFF_ARAW 0                       // 2 x 8704 = 17408
#define OFF_BH   (2 * ASZ)               // 2 x 4608 = 9216
#define OFF_BL   (OFF_BH + 2 * BSZ)      // 2 x 4608
#define SMEM_F   (OFF_BL + 2 * BSZ)      // 35840 floats
#define SMEM_BYTES (SMEM_F * 4)          // 143360 B -> 1 CTA/SM

// device scratch (no cudaMalloc allowed)
__device__ float g_part_imp[NBLK][NEXP];
__device__ float g_part_p[NBLK][NEXP];
__device__ float g_wh[DDIM * NEXP];
__device__ float g_wl[DDIM * NEXP];
__device__ int   g_ctr;

__device__ __forceinline__ uint32_t tf32_of(float f) {
    uint32_t u;
    asm("cvt.rna.tf32.f32 %0, %1;" : "=r"(u) : "f"(f));
    return u;
}
__device__ __forceinline__ void mma_tf32(float* c, const uint32_t* a,
                                         uint32_t b0, uint32_t b1) {
    asm volatile(
        "mma.sync.aligned.m16n8k8.row.col.f32.tf32.tf32.f32 "
        "{%0,%1,%2,%3}, {%4,%5,%6,%7}, {%8,%9}, {%0,%1,%2,%3};"
        : "+f"(c[0]), "+f"(c[1]), "+f"(c[2]), "+f"(c[3])
        : "r"(a[0]), "r"(a[1]), "r"(a[2]), "r"(a[3]), "r"(b0), "r"(b1));
}
__device__ __forceinline__ bool gtv(float a, int ia, float b, int ib) {
    return (a > b) || (a == b && ia < ib);
}

// ---- prologue: split W once into tf32 hi/lo (RNA quality)
__global__ void __launch_bounds__(256) wconv(const float* __restrict__ W) {
    const int idx = blockIdx.x * 256 + threadIdx.x;   // 512 blocks -> 131072 elems
    const float w = W[idx];
    const float hf = __uint_as_float(tf32_of(w));
    g_wh[idx] = hf;
    g_wl[idx] = __uint_as_float(tf32_of(w - hf));
}

__global__ void __launch_bounds__(NTHR)
router_main(const float* __restrict__ x, const float* __restrict__ bias_g,
            const float* __restrict__ noise, float* __restrict__ out) {
    extern __shared__ __align__(16) float sm[];

    const int tid  = threadIdx.x;
    const int lane = tid & 31;
    const int w    = tid >> 5;    // warp 0..31
    const int mg   = w & 7;       // m-tile: rows [mg*16, mg*16+16)
    const int ng   = w >> 3;      // n-group 0..3: cols [ng*16, ng*16+16)
    const int g    = lane >> 2;   // 0..7
    const int l4   = lane & 3;    // 0..3
    const int bm   = blockIdx.x * TM;

    // staging A: 8 threads per token row, 8 consecutive floats each
    const int tokS = tid >> 3;         // 0..127
    const int qS   = (tid & 7) * 8;    // 0..56
    const float* xsrc = x + (size_t)(bm + tokS) * DDIM + qS;
    // staging B: thread copies 4 floats of row kB at qB (wh and wl)
    const int kB = tid >> 4;           // 0..63
    const int qB = (tid & 15) * 4;     // 0..60

    auto stage = [&](int c) {
        if (c < NCHUNK) {
            float* ad = sm + OFF_ARAW + (c & 1) * ASZ + tokS * APITCH + qS;
            const float* as = xsrc + c * KC;
            __pipeline_memcpy_async(ad, as, 16);
            __pipeline_memcpy_async(ad + 4, as + 4, 16);
            const size_t wsrc = (size_t)(c * KC + kB) * NEXP + qB;
            const int wdst = kB * BPITCH + qB;
            __pipeline_memcpy_async(sm + OFF_BH + (c & 1) * BSZ + wdst, g_wh + wsrc, 16);
            __pipeline_memcpy_async(sm + OFF_BL + (c & 1) * BSZ + wdst, g_wl + wsrc, 16);
        }
        __pipeline_commit();
    };

    float acc[2][4];
#pragma unroll
    for (int ni = 0; ni < 2; ni++)
#pragma unroll
        for (int r = 0; r < 4; r++) acc[ni][r] = 0.f;

    stage(0); stage(1);
    __pipeline_wait_prior(1);   // chunk 0 landed (thread-local)
    __syncthreads();            // chunk 0 visible block-wide

    const int r0 = mg * 16 + g;

    for (int c = 0; c < NCHUNK; ++c) {
        // invariant: chunk c visible block-wide; chunk c+1 in flight
        const float* Ar = sm + OFF_ARAW + (c & 1) * ASZ;
        const float* Bh = sm + OFF_BH + (c & 1) * BSZ;
        const float* Bl = sm + OFF_BL + (c & 1) * BSZ;

#pragma unroll
        for (int ks = 0; ks < KC / 8; ks++) {
            const int kk = ks * 8 + l4;
            // A fragment: raw f32 loads, exact mask split (ah | al both valid tf32)
            const float f0 = Ar[r0 * APITCH + kk];
            const float f1 = Ar[(r0 + 8) * APITCH + kk];
            const float f2 = Ar[r0 * APITCH + kk + 4];
            const float f3 = Ar[(r0 + 8) * APITCH + kk + 4];
            uint32_t ah[4], al[4];
            ah[0] = __float_as_uint(f0) & TF32_MASK;
            ah[1] = __float_as_uint(f1) & TF32_MASK;
            ah[2] = __float_as_uint(f2) & TF32_MASK;
            ah[3] = __float_as_uint(f3) & TF32_MASK;
            al[0] = __float_as_uint(f0 - __uint_as_float(ah[0])) & TF32_MASK;
            al[1] = __float_as_uint(f1 - __uint_as_float(ah[1])) & TF32_MASK;
            al[2] = __float_as_uint(f2 - __uint_as_float(ah[2])) & TF32_MASK;
            al[3] = __float_as_uint(f3 - __uint_as_float(ah[3])) & TF32_MASK;
#pragma unroll
            for (int ni = 0; ni < 2; ni++) {
                const int bo = ng * 16 + ni * 8 + g;
                const uint32_t bh0 = __float_as_uint(Bh[kk * BPITCH + bo]);
                const uint32_t bh1 = __float_as_uint(Bh[(kk + 4) * BPITCH + bo]);
                const uint32_t bl0 = __float_as_uint(Bl[kk * BPITCH + bo]);
                const uint32_t bl1 = __float_as_uint(Bl[(kk + 4) * BPITCH + bo]);
                mma_tf32(acc[ni], ah, bh0, bh1);
                mma_tf32(acc[ni], ah, bl0, bl1);
                mma_tf32(acc[ni], al, bh0, bh1);
            }
        }

        __syncthreads();           // all reads of buf (c&1) complete block-wide
        stage(c + 2);              // overwrite buf (c&1) (async)
        __pipeline_wait_prior(1);  // thread-local: chunk c+1 landed
        __syncthreads();           // cross-thread: chunk c+1 visible
    }

    // ---- store C into Ls[128][66] (reuses ARAW region; loop ended with sync)
    float* Ls = sm;
#pragma unroll
    for (int ni = 0; ni < 2; ni++) {
        const int row = mg * 16 + g;
        const int col = ng * 16 + ni * 8 + l4 * 2;
        *(float2*)(Ls + row * 66 + col) = make_float2(acc[ni][0], acc[ni][1]);
        *(float2*)(Ls + (row + 8) * 66 + col) = make_float2(acc[ni][2], acc[ni][3]);
    }
    __syncthreads();

    // ---- per-token epilogue: warp w handles tokens [w*4, w*4+4)
    const int e0 = 2 * lane;
    const int e1 = 2 * lane + 1;
    const float bb0 = __ldg(bias_g + e0);
    const float bb1 = __ldg(bias_g + e1);

    float imp0 = 0.f, imp1 = 0.f, pa0 = 0.f, pa1 = 0.f;

    for (int tt = 0; tt < 4; ++tt) {
        const int tl = w * 4 + tt;
        const int t  = bm + tl;
        const float2 L2 = *(const float2*)(Ls + tl * 66 + e0);
        const float l0 = L2.x + bb0, l1 = L2.y + bb1;

        float mx = fmaxf(l0, l1);
#pragma unroll
        for (int off = 16; off; off >>= 1)
            mx = fmaxf(mx, __shfl_xor_sync(0xffffffffu, mx, off));
        const float s0 = __expf(l0 - mx);
        const float s1 = __expf(l1 - mx);
        float ss = s0 + s1;
#pragma unroll
        for (int off = 16; off; off >>= 1)
            ss += __shfl_xor_sync(0xffffffffu, ss, off);
        const float rs = 1.0f / ss;
        imp0 += s0 * rs;
        imp1 += s1 * rs;

        const float2 nz = *(const float2*)(noise + (size_t)t * NEXP + e0);
        const float n0 = fmaf(NOISE_STD, nz.x, l0);
        const float n1 = fmaf(NOISE_STD, nz.y, l1);
        float v1, v2;
        int i1, i2;
        if (n0 >= n1) { v1 = n0; i1 = e0; v2 = n1; i2 = e1; }
        else          { v1 = n1; i1 = e1; v2 = n0; i2 = e0; }
#pragma unroll
        for (int off = 16; off; off >>= 1) {
            const float ov1 = __shfl_xor_sync(0xffffffffu, v1, off);
            const int   oi1 = __shfl_xor_sync(0xffffffffu, i1, off);
            const float ov2 = __shfl_xor_sync(0xffffffffu, v2, off);
            const int   oi2 = __shfl_xor_sync(0xffffffffu, i2, off);
            if (gtv(ov1, oi1, v1, i1)) {
                if (gtv(v1, i1, ov2, oi2)) { v2 = v1; i2 = i1; }
                else                       { v2 = ov2; i2 = oi2; }
                v1 = ov1; i1 = oi1;
            } else if (gtv(ov1, oi1, v2, i2)) {
                v2 = ov1; i2 = oi1;
            }
        }

        const float ee = __expf(v2 - v1);
        const float g1 = 1.0f / (1.0f + ee);
        const float g2 = ee * g1;

        const float z0 = (v2 - l0) * 64.0f;
        const float z1 = (v2 - l1) * 64.0f;
        pa0 += normcdff(-z0);
        pa1 += normcdff(-z1);

        if (lane == 0) {
            out[2 * t + 0] = g1;
            out[2 * t + 1] = g2;
            out[2 * NTOK + 2 * t + 0] = (float)i1;
            out[2 * NTOK + 2 * t + 1] = (float)i2;
        }
    }

    // ---- block partials (deterministic layout; 32 warps)
    float* redI = sm + 8448;          // [32][64]
    float* redP = sm + 8448 + 2048;   // [32][64]
    redI[w * 64 + e0] = imp0;
    redI[w * 64 + e1] = imp1;
    redP[w * 64 + e0] = pa0;
    redP[w * 64 + e1] = pa1;
    __syncthreads();
    if (tid < NEXP) {
        float si = 0.f, sp = 0.f;
#pragma unroll
        for (int r = 0; r < 32; r++) {
            si += redI[r * 64 + tid];
            sp += redP[r * 64 + tid];
        }
        g_part_imp[blockIdx.x][tid] = si;
        g_part_p[blockIdx.x][tid]   = sp;
    }

    // ---- last CTA computes aux loss (fixed-order sums -> deterministic)
    __threadfence();
    __shared__ int s_ticket;
    if (tid == 0) s_ticket = atomicAdd(&g_ctr, 1);
    __syncthreads();
    if (s_ticket == NBLK - 1) {
        const int e = tid & 63;
        const int h = tid >> 6;  // 0..15
        float si = 0.f, sp = 0.f;
        for (int b = h * (NBLK / 16); b < (h + 1) * (NBLK / 16); ++b) {
            si += g_part_imp[b][e];
            sp += g_part_p[b][e];
        }
        float* sa = sm;          // reuse smem (post-sync); [16][64]
        float* sb = sm + 1024;
        __syncthreads();
        sa[h * 64 + e] = si;
        sb[h * 64 + e] = sp;
        __syncthreads();
        if (tid == 0) {
            float ma = 0.f, mp = 0.f;
            float va = 0.f, vp = 0.f;
            float ia[NEXP], pa[NEXP];
            for (int i = 0; i < NEXP; i++) {
                float s1 = 0.f, s2 = 0.f;
                for (int hh = 0; hh < 16; hh++) {
                    s1 += sa[hh * 64 + i];
                    s2 += sb[hh * 64 + i];
                }
                ia[i] = s1;
                pa[i] = s2 * (1.0f / NTOK);
                ma += ia[i];
                mp += pa[i];
            }
            ma *= (1.0f / NEXP);
            mp *= (1.0f / NEXP);
            for (int i = 0; i < NEXP; i++) {
                const float da = ia[i] - ma;
                const float dp = pa[i] - mp;
                va += da * da;
                vp += dp * dp;
            }
            va *= (1.0f / (NEXP - 1));  // ddof=1
            vp *= (1.0f / (NEXP - 1));
            const float il = va / ((ma + 1e-8f) * (ma + 1e-8f));
            const float ll = vp / ((mp + 1e-8f) * (mp + 1e-8f));
            g_ctr = 0;  // reset for next graph replay
            out[4 * NTOK] = 0.5f * (il + ll);
        }
    }
}

extern "C" void kernel_launch(void* const* d_in, const int* in_sizes, int n_in,
                              void* d_out, int out_size) {
    const float* x     = (const float*)d_in[0];
    const float* W     = (const float*)d_in[1];
    const float* b     = (const float*)d_in[2];
    const float* noise = (const float*)d_in[3];
    float* out = (float*)d_out;

    cudaFuncSetAttribute(router_main, cudaFuncAttributeMaxDynamicSharedMemorySize, SMEM_BYTES);
    wconv<<<512, 256>>>(W);
    router_main<<<NBLK, NTHR, SMEM_BYTES>>>(x, b, noise, out);
}

// round 13
// speedup vs baseline: 1.5394x; 1.3872x over previous
#include <cuda_runtime.h>
#include <cuda_pipeline.h>
#include <math.h>
#include <stdint.h>

#define NTOK 16384
#define DDIM 2048
#define NEXP 64
#define TM   128
#define NBLK (NTOK / TM)      // 128 blocks
#define NTHR 1024             // 32 warps, 8 per SMSP
#define KC   64
#define NCHUNK (DDIM / KC)    // 32 chunks
#define APITCH 72             // A smem pitch (floats): conflict-free LDS.64 frags
#define ASZ (TM * APITCH)     // 9216 f per buffer
#define BPITCH 72             // packed-B pitch (u32): conflict-free scalar LDS
#define BSZ (32 * BPITCH)     // 2304 u32 per buffer (32 k2-rows per chunk)
#define NOISE_STD (1.0f / 64.0f)

// smem float offsets (double-buffered, depth 2)
#define OFF_ARAW 0                       // 2 x 9216 = 18432
#define OFF_BH   (2 * ASZ)               // 2 x 2304 = 4608
#define OFF_BL   (OFF_BH + 2 * BSZ)      // 2 x 2304
#define SMEM_F   (OFF_BL + 2 * BSZ)      // 27648 floats
#define SMEM_BYTES (SMEM_F * 4)          // 110592 B -> 1 CTA/SM

// device scratch (no cudaMalloc allowed)
__device__ float    g_part_imp[NBLK][NEXP];
__device__ float    g_part_p[NBLK][NEXP];
// packed W bf16x2: g_wbh[k2*64+n] = {lo: bf16(W[2k2][n]), hi: bf16(W[2k2+1][n])}
__device__ uint32_t g_wbh[(DDIM / 2) * NEXP];
__device__ uint32_t g_wbl[(DDIM / 2) * NEXP];
__device__ int      g_ctr;

// pack two fp32 -> bf16x2 (RN): lower half = e0, upper half = e1
__device__ __forceinline__ uint32_t pack_bf16x2(float e0, float e1) {
    uint32_t r;
    asm("cvt.rn.satfinite.bf16x2.f32 %0, %1, %2;" : "=r"(r) : "f"(e1), "f"(e0));
    return r;
}
__device__ __forceinline__ void mma_bf16(float* c, const uint32_t* a,
                                         uint32_t b0, uint32_t b1) {
    asm volatile(
        "mma.sync.aligned.m16n8k16.row.col.f32.bf16.bf16.f32 "
        "{%0,%1,%2,%3}, {%4,%5,%6,%7}, {%8,%9}, {%0,%1,%2,%3};"
        : "+f"(c[0]), "+f"(c[1]), "+f"(c[2]), "+f"(c[3])
        : "r"(a[0]), "r"(a[1]), "r"(a[2]), "r"(a[3]), "r"(b0), "r"(b1));
}
// split a float2 (consecutive k) into bf16x2 hi and lo parts
__device__ __forceinline__ void split_pair(float2 p, uint32_t& hi2, uint32_t& lo2) {
    hi2 = pack_bf16x2(p.x, p.y);
    const float h0 = __uint_as_float(hi2 << 16);
    const float h1 = __uint_as_float(hi2 & 0xFFFF0000u);
    lo2 = pack_bf16x2(p.x - h0, p.y - h1);
}
__device__ __forceinline__ bool gtv(float a, int ia, float b, int ib) {
    return (a > b) || (a == b && ia < ib);
}

// ---- prologue: split W into packed bf16x2 hi/lo pairs (k-pairs in one u32)
__global__ void __launch_bounds__(256) wconv(const float* __restrict__ W) {
    const int idx = blockIdx.x * 256 + threadIdx.x;   // 256 blocks -> 65536
    const int k2 = idx >> 6, n = idx & 63;
    const float f0 = W[(size_t)(2 * k2) * NEXP + n];
    const float f1 = W[(size_t)(2 * k2 + 1) * NEXP + n];
    uint32_t h2, l2;
    split_pair(make_float2(f0, f1), h2, l2);
    g_wbh[k2 * 64 + n] = h2;
    g_wbl[k2 * 64 + n] = l2;
}

__global__ void __launch_bounds__(NTHR)
router_main(const float* __restrict__ x, const float* __restrict__ bias_g,
            const float* __restrict__ noise, float* __restrict__ out) {
    extern __shared__ __align__(16) float sm[];

    const int tid  = threadIdx.x;
    const int lane = tid & 31;
    const int w    = tid >> 5;    // warp 0..31
    const int mg   = w & 7;       // m-tile: rows [mg*16, mg*16+16)
    const int ng   = w >> 3;      // n-group 0..3: cols [ng*16, ng*16+16)
    const int g    = lane >> 2;   // 0..7
    const int l4   = lane & 3;    // 0..3
    const int bm   = blockIdx.x * TM;

    // staging A: 8 threads per token row, 8 consecutive floats each
    const int tokS = tid >> 3;         // 0..127
    const int qS   = (tid & 7) * 8;    // 0..56
    const float* xsrc = x + (size_t)(bm + tokS) * DDIM + qS;
    // staging B: thread copies 2 u32 of packed row kB2 (both hi and lo arrays)
    const int kB2 = tid >> 5;          // 0..31
    const int qB  = (tid & 31) * 2;    // 0..62

    uint32_t* Bh_base = (uint32_t*)(sm + OFF_BH);
    uint32_t* Bl_base = (uint32_t*)(sm + OFF_BL);

    auto stage = [&](int c) {
        if (c < NCHUNK) {
            float* ad = sm + OFF_ARAW + (c & 1) * ASZ + tokS * APITCH + qS;
            const float* as = xsrc + c * KC;
            __pipeline_memcpy_async(ad, as, 16);
            __pipeline_memcpy_async(ad + 4, as + 4, 16);
            const int bsrc = c * (KC / 2) * 64 + kB2 * 64 + qB;
            const int bdst = kB2 * BPITCH + qB;
            __pipeline_memcpy_async(Bh_base + (c & 1) * BSZ + bdst, g_wbh + bsrc, 8);
            __pipeline_memcpy_async(Bl_base + (c & 1) * BSZ + bdst, g_wbl + bsrc, 8);
        }
        __pipeline_commit();
    };

    float acc[2][4];
#pragma unroll
    for (int ni = 0; ni < 2; ni++)
#pragma unroll
        for (int r = 0; r < 4; r++) acc[ni][r] = 0.f;

    stage(0); stage(1);
    __pipeline_wait_prior(1);   // chunk 0 landed (thread-local)
    __syncthreads();            // chunk 0 visible block-wide

    const int r0 = mg * 16 + g;

    for (int c = 0; c < NCHUNK; ++c) {
        // invariant: chunk c visible block-wide; chunk c+1 in flight
        const float* Ar = sm + OFF_ARAW + (c & 1) * ASZ;
        const uint32_t* Bh = Bh_base + (c & 1) * BSZ;
        const uint32_t* Bl = Bl_base + (c & 1) * BSZ;

#pragma unroll
        for (int ks = 0; ks < KC / 16; ks++) {      // k16 steps
            const int k0 = ks * 16 + 2 * l4;
            // A fragment: 4x LDS.64 of consecutive k-pairs, bf16 split in regs
            const float2 p0 = *(const float2*)(Ar + r0 * APITCH + k0);
            const float2 p1 = *(const float2*)(Ar + (r0 + 8) * APITCH + k0);
            const float2 p2 = *(const float2*)(Ar + r0 * APITCH + k0 + 8);
            const float2 p3 = *(const float2*)(Ar + (r0 + 8) * APITCH + k0 + 8);
            uint32_t ah[4], al[4];
            split_pair(p0, ah[0], al[0]);
            split_pair(p1, ah[1], al[1]);
            split_pair(p2, ah[2], al[2]);
            split_pair(p3, ah[3], al[3]);
            // B fragments: rows k2 = ks*8 + l4 (+4); packed quads, 1 LDS each
            const int kr = ks * 8 + l4;
#pragma unroll
            for (int ni = 0; ni < 2; ni++) {
                const int n = ng * 16 + ni * 8 + g;
                const uint32_t bh0 = Bh[kr * BPITCH + n];
                const uint32_t bh1 = Bh[(kr + 4) * BPITCH + n];
                const uint32_t bl0 = Bl[kr * BPITCH + n];
                const uint32_t bl1 = Bl[(kr + 4) * BPITCH + n];
                mma_bf16(acc[ni], ah, bh0, bh1);   // hh
                mma_bf16(acc[ni], ah, bl0, bl1);   // hl
                mma_bf16(acc[ni], al, bh0, bh1);   // lh
            }
        }

        __syncthreads();           // all reads of buf (c&1) complete block-wide
        stage(c + 2);              // overwrite buf (c&1) (async)
        __pipeline_wait_prior(1);  // thread-local: chunk c+1 landed
        __syncthreads();           // cross-thread: chunk c+1 visible
    }

    // ---- store C into Ls[128][66] (reuses ARAW region; loop ended with sync)
    float* Ls = sm;
#pragma unroll
    for (int ni = 0; ni < 2; ni++) {
        const int row = mg * 16 + g;
        const int col = ng * 16 + ni * 8 + l4 * 2;
        *(float2*)(Ls + row * 66 + col) = make_float2(acc[ni][0], acc[ni][1]);
        *(float2*)(Ls + (row + 8) * 66 + col) = make_float2(acc[ni][2], acc[ni][3]);
    }
    __syncthreads();

    // ---- per-token epilogue: warp w handles tokens [w*4, w*4+4)
    const int e0 = 2 * lane;
    const int e1 = 2 * lane + 1;
    const float bb0 = __ldg(bias_g + e0);
    const float bb1 = __ldg(bias_g + e1);

    float imp0 = 0.f, imp1 = 0.f, pa0 = 0.f, pa1 = 0.f;

    for (int tt = 0; tt < 4; ++tt) {
        const int tl = w * 4 + tt;
        const int t  = bm + tl;
        const float2 L2 = *(const float2*)(Ls + tl * 66 + e0);
        const float l0 = L2.x + bb0, l1 = L2.y + bb1;

        float mx = fmaxf(l0, l1);
#pragma unroll
        for (int off = 16; off; off >>= 1)
            mx = fmaxf(mx, __shfl_xor_sync(0xffffffffu, mx, off));
        const float s0 = __expf(l0 - mx);
        const float s1 = __expf(l1 - mx);
        float ss = s0 + s1;
#pragma unroll
        for (int off = 16; off; off >>= 1)
            ss += __shfl_xor_sync(0xffffffffu, ss, off);
        const float rs = 1.0f / ss;
        imp0 += s0 * rs;
        imp1 += s1 * rs;

        const float2 nz = *(const float2*)(noise + (size_t)t * NEXP + e0);
        const float n0 = fmaf(NOISE_STD, nz.x, l0);
        const float n1 = fmaf(NOISE_STD, nz.y, l1);
        float v1, v2;
        int i1, i2;
        if (n0 >= n1) { v1 = n0; i1 = e0; v2 = n1; i2 = e1; }
        else          { v1 = n1; i1 = e1; v2 = n0; i2 = e0; }
#pragma unroll
        for (int off = 16; off; off >>= 1) {
            const float ov1 = __shfl_xor_sync(0xffffffffu, v1, off);
            const int   oi1 = __shfl_xor_sync(0xffffffffu, i1, off);
            const float ov2 = __shfl_xor_sync(0xffffffffu, v2, off);
            const int   oi2 = __shfl_xor_sync(0xffffffffu, i2, off);
            if (gtv(ov1, oi1, v1, i1)) {
                if (gtv(v1, i1, ov2, oi2)) { v2 = v1; i2 = i1; }
                else                       { v2 = ov2; i2 = oi2; }
                v1 = ov1; i1 = oi1;
            } else if (gtv(ov1, oi1, v2, i2)) {
                v2 = ov1; i2 = oi1;
            }
        }

        const float ee = __expf(v2 - v1);
        const float g1 = 1.0f / (1.0f + ee);
        const float g2 = ee * g1;

        const float z0 = (v2 - l0) * 64.0f;
        const float z1 = (v2 - l1) * 64.0f;
        pa0 += normcdff(-z0);
        pa1 += normcdff(-z1);

        if (lane == 0) {
            out[2 * t + 0] = g1;
            out[2 * t + 1] = g2;
            out[2 * NTOK + 2 * t + 0] = (float)i1;
            out[2 * NTOK + 2 * t + 1] = (float)i2;
        }
    }

    // ---- block partials (deterministic layout; 32 warps)
    float* redI = sm + 8448;          // [32][64]
    float* redP = sm + 8448 + 2048;   // [32][64]
    redI[w * 64 + e0] = imp0;
    redI[w * 64 + e1] = imp1;
    redP[w * 64 + e0] = pa0;
    redP[w * 64 + e1] = pa1;
    __syncthreads();
    if (tid < NEXP) {
        float si = 0.f, sp = 0.f;
#pragma unroll
        for (int r = 0; r < 32; r++) {
            si += redI[r * 64 + tid];
            sp += redP[r * 64 + tid];
        }
        g_part_imp[blockIdx.x][tid] = si;
        g_part_p[blockIdx.x][tid]   = sp;
    }

    // ---- last CTA computes aux loss (fixed-order sums -> deterministic)
    __threadfence();
    __shared__ int s_ticket;
    if (tid == 0) s_ticket = atomicAdd(&g_ctr, 1);
    __syncthreads();
    if (s_ticket == NBLK - 1) {
        const int e = tid & 63;
        const int h = tid >> 6;  // 0..15
        float si = 0.f, sp = 0.f;
        for (int b = h * (NBLK / 16); b < (h + 1) * (NBLK / 16); ++b) {
            si += g_part_imp[b][e];
            sp += g_part_p[b][e];
        }
        float* sa = sm;          // reuse smem (post-sync); [16][64]
        float* sb = sm + 1024;
        __syncthreads();
        sa[h * 64 + e] = si;
        sb[h * 64 + e] = sp;
        __syncthreads();
        if (tid == 0) {
            float ma = 0.f, mp = 0.f;
            float va = 0.f, vp = 0.f;
            float ia[NEXP], pa[NEXP];
            for (int i = 0; i < NEXP; i++) {
                float s1 = 0.f, s2 = 0.f;
                for (int hh = 0; hh < 16; hh++) {
                    s1 += sa[hh * 64 + i];
                    s2 += sb[hh * 64 + i];
                }
                ia[i] = s1;
                pa[i] = s2 * (1.0f / NTOK);
                ma += ia[i];
                mp += pa[i];
            }
            ma *= (1.0f / NEXP);
            mp *= (1.0f / NEXP);
            for (int i = 0; i < NEXP; i++) {
                const float da = ia[i] - ma;
                const float dp = pa[i] - mp;
                va += da * da;
                vp += dp * dp;
            }
            va *= (1.0f / (NEXP - 1));  // ddof=1
            vp *= (1.0f / (NEXP - 1));
            const float il = va / ((ma + 1e-8f) * (ma + 1e-8f));
            const float ll = vp / ((mp + 1e-8f) * (mp + 1e-8f));
            g_ctr = 0;  // reset for next graph replay
            out[4 * NTOK] = 0.5f * (il + ll);
        }
    }
}

extern "C" void kernel_launch(void* const* d_in, const int* in_sizes, int n_in,
                              void* d_out, int out_size) {
    const float* x     = (const float*)d_in[0];
    const float* W     = (const float*)d_in[1];
    const float* b     = (const float*)d_in[2];
    const float* noise = (const float*)d_in[3];
    float* out = (float*)d_out;

    cudaFuncSetAttribute(router_main, cudaFuncAttributeMaxDynamicSharedMemorySize, SMEM_BYTES);
    wconv<<<256, 256>>>(W);
    router_main<<<NBLK, NTHR, SMEM_BYTES>>>(x, b, noise, out);
}